// round 1
// baseline (speedup 1.0000x reference)
#include <cuda_runtime.h>
#include <cuda_bf16.h>
#include <math.h>

// Problem constants (match reference_code)
#define BS_   64
#define NQ_   300
#define NC_   2
#define T_    1280            // 64 * 20 targets
#define ROWS_ (BS_ * NQ_)     // 19200
#define RPB_  16              // rows per block
#define THREADS_ 320          // 1280 cols / 4 per thread

// cost = COST_SPAN*L1 + COST_GIOU*(-giou) + COST_CLASS*(-softmax[:,0]) + COST_REFERENCE*refdist
// all weights = 1.0

__global__ __launch_bounds__(THREADS_, 4)
void hungarian_cost_kernel(const float* __restrict__ logits,   // [ROWS_, 2]
                           const float* __restrict__ spans,    // [ROWS_, 2] (cx, w)
                           const float* __restrict__ tgt,      // [T_, 2]    (cx, w)
                           const float* __restrict__ refp,     // [ROWS_, 2]
                           float* __restrict__ out)            // [ROWS_, T_]
{
    __shared__ float s_cx[RPB_], s_w[RPB_], s_x1[RPB_], s_x2[RPB_], s_rc[RPB_];

    const int t    = threadIdx.x;          // 0..319, owns columns 4t..4t+3
    const int row0 = blockIdx.x * RPB_;

    // ---- load this thread's 4 target tuples once; reused for all 16 rows ----
    // tgt is [1280,2] contiguous floats; cols 4t..4t+3 -> floats [8t, 8t+8)
    const float4 ta = __ldg(reinterpret_cast<const float4*>(tgt) + 2 * t);
    const float4 tb = __ldg(reinterpret_cast<const float4*>(tgt) + 2 * t + 1);

    float tcx[4], tw[4], tx1[4], tx2[4];
    tcx[0] = ta.x; tw[0] = ta.y;
    tcx[1] = ta.z; tw[1] = ta.w;
    tcx[2] = tb.x; tw[2] = tb.y;
    tcx[3] = tb.z; tw[3] = tb.w;
#pragma unroll
    for (int i = 0; i < 4; ++i) {
        tx1[i] = tcx[i] - 0.5f * tw[i];
        tx2[i] = tcx[i] + 0.5f * tw[i];
    }

    // ---- cooperative per-row constants (threads 0..15 each do one row) ----
    if (t < RPB_) {
        const int r = row0 + t;
        const float l0 = __ldg(logits + 2 * r);
        const float l1 = __ldg(logits + 2 * r + 1);
        const float m  = fmaxf(l0, l1);
        const float e0 = __expf(l0 - m);
        const float e1 = __expf(l1 - m);
        const float p0 = __fdividef(e0, e0 + e1);      // softmax prob of class 0

        const float cx = __ldg(spans + 2 * r);
        const float w  = __ldg(spans + 2 * r + 1);
        const float x1 = cx - 0.5f * w;
        const float x2 = cx + 0.5f * w;

        const float r0 = __ldg(refp + 2 * r);
        const float r1 = __ldg(refp + 2 * r + 1);
        const float d0 = fabsf(x1 - r0);
        const float d1 = fabsf(x2 - r1);
        const float cref = sqrtf(fmaf(d0, d0, d1 * d1));

        s_cx[t] = cx;
        s_w[t]  = w;
        s_x1[t] = x1;
        s_x2[t] = x2;
        s_rc[t] = cref - p0;   // cost_reference + cost_class (weights 1.0)
    }
    __syncthreads();

    // ---- main loop: 16 rows, 4 columns each, one float4 store per row ----
#pragma unroll 4
    for (int rr = 0; rr < RPB_; ++rr) {
        const float cx = s_cx[rr];
        const float w  = s_w[rr];
        const float x1 = s_x1[rr];
        const float x2 = s_x2[rr];
        const float rc = s_rc[rr];

        float v[4];
#pragma unroll
        for (int i = 0; i < 4; ++i) {
            // L1 span cost in (cx, w)
            const float cspan = fabsf(cx - tcx[i]) + fabsf(w - tw[i]);
            // 1D GIoU in (x1, x2); area_a = w, area_b = tw
            const float lt    = fmaxf(x1, tx1[i]);
            const float rb    = fminf(x2, tx2[i]);
            const float inter = fmaxf(rb - lt, 0.0f);
            const float uni   = w + tw[i] - inter;
            const float left  = fminf(x1, tx1[i]);
            const float right = fmaxf(x2, tx2[i]);
            const float enc   = fmaxf(right - left, 0.0f);
            const float giou  = __fdividef(inter, uni)
                              - __fdividef(enc - uni, enc);
            v[i] = cspan - giou + rc;
        }

        float4 o = make_float4(v[0], v[1], v[2], v[3]);
        reinterpret_cast<float4*>(out + (size_t)(row0 + rr) * T_)[t] = o;
    }
}

extern "C" void kernel_launch(void* const* d_in, const int* in_sizes, int n_in,
                              void* d_out, int out_size) {
    const float* logits = (const float*)d_in[0];  // pred_logits [64,300,2]
    const float* spans  = (const float*)d_in[1];  // pred_spans  [64,300,2]
    const float* tgt    = (const float*)d_in[2];  // tgt_spans   [1280,2]
    const float* refp   = (const float*)d_in[3];  // ref_points  [64,300,2]
    float* out = (float*)d_out;                   // [64,300,1280] fp32

    const int blocks = ROWS_ / RPB_;              // 1200
    hungarian_cost_kernel<<<blocks, THREADS_>>>(logits, spans, tgt, refp, out);
}